// round 10
// baseline (speedup 1.0000x reference)
#include <cuda_runtime.h>

#define BB 2
#define CC 64
#define HH 48
#define WWn 48
#define LL 48
#define HWn (HH*WWn)            // 2304
#define SS (HH*WWn*LL)          // 110592
#define GHn 24
#define GSS (GHn*GHn*GHn)       // 13824
#define NSITES (BB*HWn)         // 4608
#define TOTAL (BB*CC*SS)        // 14155776

// ---------------- scratch ----------------
__device__ float g_tx[TOTAL];
__device__ float g_tg[TOTAL];
__device__ float g_tgl[BB*CC*GSS];
__device__ unsigned g_min_p_key;
__device__ unsigned g_min_d_key;
__device__ float g_sitechan[NSITES*CC];
__device__ float g_sitesum[NSITES];
__device__ float g_inv1[BB*CC];
__device__ float g_inv2[BB];

__device__ __forceinline__ unsigned fkey(float f) {
    unsigned u = __float_as_uint(f);
    return (u & 0x80000000u) ? ~u : (u | 0x80000000u);
}
__device__ __forceinline__ float funkey(unsigned k) {
    unsigned u = (k & 0x80000000u) ? (k ^ 0x80000000u) : ~k;
    return __uint_as_float(u);
}

// ---------------- channel-mix GEMM: 128 sites x 64 outs per block ----------
#define CM_SMEM ((64*68 + 64 + 64*132)*4)
__global__ __launch_bounds__(128, 4) void k_chanmix(
        const float* __restrict__ in, const float* __restrict__ Wm,
        const float* __restrict__ bias, int which, int Ssz) {
    extern __shared__ float dyn[];
    float* Wt  = dyn;             // 64*68
    float* bsm = Wt + 64*68;      // 64
    float* Xs  = bsm + 64;        // 64*132
    int tid = threadIdx.x;

    // fold the min-key init into the first kernel (g-side, block (0,0))
    if (which && blockIdx.x == 0 && blockIdx.y == 0 && tid == 0) {
        g_min_p_key = 0xFFFFFFFFu;
        g_min_d_key = 0xFFFFFFFFu;
    }

    for (int i = tid; i < 4096; i += 128) {
        int o = i >> 6, c = i & 63;
        Wt[c*68 + o] = Wm[i];
    }
    if (tid < 64) bsm[tid] = bias[tid];

    int b = blockIdx.y;
    size_t sbase = (size_t)b * CC * Ssz + (size_t)blockIdx.x * 128;
    const float* src = in + sbase;
    for (int i = tid; i < 64*32; i += 128) {
        int c = i >> 5, sv = i & 31;
        float4 v = *(const float4*)(src + (size_t)c*Ssz + sv*4);
        *(float4*)&Xs[c*132 + sv*4] = v;
    }
    __syncthreads();

    int og = tid & 3;
    int sg = tid >> 2;
    float acc[16][4];
#pragma unroll
    for (int j = 0; j < 16; j++) {
        float bv = bsm[og*16 + j];
        acc[j][0]=bv; acc[j][1]=bv; acc[j][2]=bv; acc[j][3]=bv;
    }

#pragma unroll 4
    for (int c = 0; c < 64; c++) {
        float4 xv = *(const float4*)&Xs[c*132 + sg*4];
        float xk[4] = {xv.x, xv.y, xv.z, xv.w};
#pragma unroll
        for (int q = 0; q < 4; q++) {
            float4 wv = *(const float4*)&Wt[c*68 + og*16 + q*4];
            float wk[4] = {wv.x, wv.y, wv.z, wv.w};
#pragma unroll
            for (int jj = 0; jj < 4; jj++)
#pragma unroll
                for (int kk = 0; kk < 4; kk++)
                    acc[q*4+jj][kk] = fmaf(wk[jj], xk[kk], acc[q*4+jj][kk]);
        }
    }

    float* outp = (which ? (float*)g_tgl : (float*)g_tx) + sbase;
#pragma unroll
    for (int j = 0; j < 16; j++) {
        int o = og*16 + j;
        float4 v = make_float4(acc[j][0], acc[j][1], acc[j][2], acc[j][3]);
        *(float4*)(outp + (size_t)o*Ssz + sg*4) = v;
    }
}

// ---------------- trilinear x2 upsample -------------------------------------
__global__ void k_upsample() {
    __shared__ float ph[24*25];
    int h  = blockIdx.x;
    int bc = blockIdx.y;

    int kh = h >> 1;
    int hf = (h & 1) ? (kh+1 > 23 ? 23 : kh+1) : (kh-1 < 0 ? 0 : kh-1);

    const float* bnear = g_tgl + (size_t)bc * GSS + kh*576;
    const float* bfar  = g_tgl + (size_t)bc * GSS + hf*576;
    int tid = threadIdx.y * 24 + threadIdx.x;
    for (int i = tid; i < 576; i += 384) {
        int wi = i / 24, li = i - wi*24;
        ph[wi*25 + li] = 0.75f*bnear[i] + 0.25f*bfar[i];
    }
    __syncthreads();

    int kl = threadIdx.x;
    int lm = kl-1 < 0 ? 0 : kl-1;
    int lp = kl+1 > 23 ? 23 : kl+1;

    float* orow = g_tg + (size_t)bc * SS + (size_t)h * HWn;
    for (int w = threadIdx.y; w < 48; w += 16) {
        int kw = w >> 1;
        int wf = (w & 1) ? (kw+1 > 23 ? 23 : kw+1) : (kw-1 < 0 ? 0 : kw-1);
        const float* rn = &ph[kw*25];
        const float* rf = &ph[wf*25];
        float um = 0.75f*rn[lm] + 0.25f*rf[lm];
        float uc = 0.75f*rn[kl] + 0.25f*rf[kl];
        float up = 0.75f*rn[lp] + 0.25f*rf[lp];
        float2 o;
        o.x = 0.25f*um + 0.75f*uc;
        o.y = 0.75f*uc + 0.25f*up;
        *(float2*)(orow + w*48 + 2*kl) = o;
    }
}

// ---- stats: raw = A*G^T per site (min+sum) AND elementwise tx*tg stats -----
// R7-proven shape: 2 sites per block, 8x8 tile per thread, occ 4.
#define SD_SMEM (2*2*3328*4)
__global__ __launch_bounds__(128, 4) void k_stats_d() {
    extern __shared__ float dyn[];
    float* Ab = dyn;            // [2][3328]
    float* Gb = dyn + 2*3328;
    __shared__ float rmin[4], rsum[4], pminw[4];
    int tid = threadIdx.x;

    for (int sj = 0; sj < 2; sj++) {
        int st = blockIdx.x*2 + sj;
        int b = st / HWn, hw = st - b*HWn;
        size_t gb = (size_t)b*CC*SS + (size_t)hw*LL;
        float* As = Ab + sj*3328;
        float* Gs = Gb + sj*3328;
        for (int i = tid; i < 64*12; i += 128) {
            int c = i / 12, lv = i - c*12;
            size_t off = gb + (size_t)c*SS + lv*4;
            *(float4*)&As[c*52 + lv*4] = *(const float4*)(g_tx + off);
            *(float4*)&Gs[c*52 + lv*4] = *(const float4*)(g_tg + off);
        }
    }
    __syncthreads();

    // ---- p stats: one channel-row per thread ----
    {
        int sl2 = tid >> 6, cch = tid & 63;
        const float* Ar = Ab + sl2*3328 + cch*52;
        const float* Gr = Gb + sl2*3328 + cch*52;
        float ps = 0.f, pm = 3.402823466e38f;
#pragma unroll
        for (int q = 0; q < 12; q++) {
            float4 a = *(const float4*)&Ar[q*4];
            float4 g = *(const float4*)&Gr[q*4];
            float t0 = a.x*g.x, t1 = a.y*g.y, t2 = a.z*g.z, t3 = a.w*g.w;
            ps += (t0+t1) + (t2+t3);
            pm = fminf(pm, fminf(fminf(t0,t1), fminf(t2,t3)));
        }
        g_sitechan[(size_t)(blockIdx.x*2 + sl2)*64 + cch] = ps;
#pragma unroll
        for (int off = 16; off; off >>= 1)
            pm = fminf(pm, __shfl_xor_sync(0xffffffffu, pm, off));
        if ((tid & 31) == 0) pminw[tid >> 5] = pm;
    }

    int sl = tid >> 6;
    int s  = tid & 63;
    int ti = s >> 3, tj = s & 7;
    const float* As = Ab + sl*3328;
    const float* Gs = Gb + sl*3328;

    float acc[8][8];
#pragma unroll
    for (int ii = 0; ii < 8; ii++)
#pragma unroll
        for (int jj = 0; jj < 8; jj++) acc[ii][jj] = 0.f;

    for (int l4 = 0; l4 < 12; l4++) {
#pragma unroll
        for (int half = 0; half < 2; half++) {
            float4 av[4];
#pragma unroll
            for (int k = 0; k < 4; k++)
                av[k] = *(const float4*)&As[(ti + 8*(half*4+k))*52 + l4*4];
#pragma unroll
            for (int jj = 0; jj < 8; jj++) {
                float4 gv = *(const float4*)&Gs[(tj + 8*jj)*52 + l4*4];
#pragma unroll
                for (int k = 0; k < 4; k++) {
                    int ii = half*4 + k;
                    acc[ii][jj] = fmaf(av[k].x, gv.x, acc[ii][jj]);
                    acc[ii][jj] = fmaf(av[k].y, gv.y, acc[ii][jj]);
                    acc[ii][jj] = fmaf(av[k].z, gv.z, acc[ii][jj]);
                    acc[ii][jj] = fmaf(av[k].w, gv.w, acc[ii][jj]);
                }
            }
        }
    }

    float lmin = acc[0][0], lsum = 0.f;
#pragma unroll
    for (int ii = 0; ii < 8; ii++)
#pragma unroll
        for (int jj = 0; jj < 8; jj++) {
            lmin = fminf(lmin, acc[ii][jj]);
            lsum += acc[ii][jj];
        }
#pragma unroll
    for (int off = 16; off; off >>= 1) {
        lmin = fminf(lmin, __shfl_xor_sync(0xffffffffu, lmin, off));
        lsum += __shfl_xor_sync(0xffffffffu, lsum, off);
    }
    int wid = tid >> 5, lane = tid & 31;
    if (!lane) { rmin[wid] = lmin; rsum[wid] = lsum; }
    __syncthreads();
    if (tid == 0) {
        float m = fminf(fminf(rmin[0], rmin[1]), fminf(rmin[2], rmin[3]));
        atomicMin(&g_min_d_key, fkey(m));
        float pm = fminf(fminf(pminw[0], pminw[1]), fminf(pminw[2], pminw[3]));
        atomicMin(&g_min_p_key, fkey(pm));
    }
    if (s == 0) {
        int w0 = sl*2;
        g_sitesum[blockIdx.x*2 + sl] = rsum[w0] + rsum[w0+1];
    }
}

// ------- merged reductions: blocks 0..127 = per-(b,c) p; 128..129 = d -------
__global__ void k_reduce_all() {
    __shared__ float sh[256];
    int tid = threadIdx.x;
    if (blockIdx.x < 128) {
        int bc = blockIdx.x;
        int b = bc >> 6, c = bc & 63;
        float s = 0.f;
        for (int i = tid; i < HWn; i += 256)
            s += g_sitechan[(size_t)(b*HWn + i)*64 + c];
        sh[tid] = s;
        __syncthreads();
        for (int st = 128; st > 0; st >>= 1) {
            if (tid < st) sh[tid] += sh[tid + st];
            __syncthreads();
        }
        if (tid == 0) {
            float m1 = funkey(g_min_p_key);
            g_inv1[bc] = 1.0f / (sh[0] - m1 * (float)SS);
        }
    } else {
        int b = blockIdx.x - 128;
        float s = 0.f;
        for (int i = tid; i < HWn; i += 256) s += g_sitesum[b * HWn + i];
        sh[tid] = s;
        __syncthreads();
        for (int st = 128; st > 0; st >>= 1) {
            if (tid < st) sh[tid] += sh[tid + st];
            __syncthreads();
        }
        if (tid == 0) {
            float m2 = funkey(g_min_d_key);
            g_inv2[b] = 1.0f / (sh[0] - m2 * 9437184.0f);
        }
    }
}

// -------- d (+ fused p): D = (G*(A^T X) - m2*colsum(X))*inv2 ----------------
#define KD_SMEM ((3328 + 3328 + 3264 + 48)*4)
__global__ __launch_bounds__(128, 5) void k_d(const float* __restrict__ x,
                                              float* __restrict__ outp,
                                              float* __restrict__ outd) {
    extern __shared__ float dyn[];
    float* As = dyn;            // 64*52   (phase1 input; becomes Ms)
    float* Ms = dyn;            // 48*52   overlay
    float* Xs = As + 3328;      // 64*52
    float* Gt = Xs + 3328;      // 48*68 (transposed, swizzled)
    float* cs = Gt + 3264;      // 48
    int tid = threadIdx.x;
    int site = blockIdx.x;
    int b = site / HWn, hw = site - b*HWn;
    size_t gb = (size_t)b*CC*SS + (size_t)hw*LL;

    float m1 = funkey(g_min_p_key);
    for (int i = tid; i < 64*12; i += 128) {
        int c = i / 12, lv = i - c*12;
        size_t off = gb + (size_t)c*SS + lv*4;
        float4 a  = *(const float4*)(g_tx + off);
        float4 xv = *(const float4*)(x + off);
        float4 gg = *(const float4*)(g_tg + off);
        *(float4*)&As[c*52 + lv*4] = a;
        *(float4*)&Xs[c*52 + lv*4] = xv;
        {
            float gv[4] = {gg.x, gg.y, gg.z, gg.w};
#pragma unroll
            for (int q = 0; q < 4; q++) {
                int row = lv*4 + q;
                int colp = c ^ (8 * ((row >> 3) & 3));
                Gt[row*68 + colp] = gv[q];
            }
        }
        float inv1 = g_inv1[b*64 + c];
        float4 o;
        o.x = (a.x*gg.x - m1) * xv.x * inv1;
        o.y = (a.y*gg.y - m1) * xv.y * inv1;
        o.z = (a.z*gg.z - m1) * xv.z * inv1;
        o.w = (a.w*gg.w - m1) * xv.w * inv1;
        *(float4*)(outp + off) = o;
    }
    __syncthreads();

    if (tid < 48) {
        float s = 0.f;
#pragma unroll 8
        for (int c = 0; c < 64; c++) s += Xs[c*52 + tid];
        cs[tid] = s;
    }

    // phase 1: M[lp][l] = sum_c A[c][lp] * X[c][l] (register accumulate;
    // xv loaded as 3x float2 — addresses tj*6 are 8B-aligned, banks 6*tj
    // mod 32 all distinct across the 8 tj groups -> conflict-free)
    float p1acc[3][6];
    int p1ti = tid >> 3;
    int p1tj = tid & 7;
    {
#pragma unroll
        for (int ii = 0; ii < 3; ii++)
#pragma unroll
            for (int jj = 0; jj < 6; jj++) p1acc[ii][jj] = 0.f;

#pragma unroll 4
        for (int c = 0; c < 64; c++) {
            float a0 = As[c*52 + p1ti*3 + 0];
            float a1 = As[c*52 + p1ti*3 + 1];
            float a2 = As[c*52 + p1ti*3 + 2];
            float2 x01 = *(const float2*)&Xs[c*52 + p1tj*6 + 0];
            float2 x23 = *(const float2*)&Xs[c*52 + p1tj*6 + 2];
            float2 x45 = *(const float2*)&Xs[c*52 + p1tj*6 + 4];
            float xv[6] = {x01.x, x01.y, x23.x, x23.y, x45.x, x45.y};
#pragma unroll
            for (int jj = 0; jj < 6; jj++) {
                p1acc[0][jj] = fmaf(a0, xv[jj], p1acc[0][jj]);
                p1acc[1][jj] = fmaf(a1, xv[jj], p1acc[1][jj]);
                p1acc[2][jj] = fmaf(a2, xv[jj], p1acc[2][jj]);
            }
        }
    }
    __syncthreads();

#pragma unroll
    for (int ii = 0; ii < 3; ii++)
#pragma unroll
        for (int jj = 0; jj < 6; jj++)
            Ms[(p1ti*3+ii)*52 + p1tj*6 + jj] = p1acc[ii][jj];
    __syncthreads();

    // phase 2: D[j][l] = sum_lp Gt[lp][j] * M[lp][l]
    float m2  = funkey(g_min_d_key);
    float inv = g_inv2[b];
    {
        int ti = tid >> 4;
        int tj = tid & 15;
        float acc[8][3];
#pragma unroll
        for (int k = 0; k < 8; k++)
#pragma unroll
            for (int m = 0; m < 3; m++) acc[k][m] = 0.f;

#pragma unroll 4
        for (int lp = 0; lp < 48; lp++) {
            int jbase = (ti*8) ^ (8 * ((lp >> 3) & 3));
            float4 gA = *(const float4*)&Gt[lp*68 + jbase];
            float4 gB = *(const float4*)&Gt[lp*68 + jbase + 4];
            float gk[8] = {gA.x,gA.y,gA.z,gA.w,gB.x,gB.y,gB.z,gB.w};
            float q0 = Ms[lp*52 + tj*3 + 0];
            float q1 = Ms[lp*52 + tj*3 + 1];
            float q2 = Ms[lp*52 + tj*3 + 2];
#pragma unroll
            for (int k = 0; k < 8; k++) {
                acc[k][0] = fmaf(gk[k], q0, acc[k][0]);
                acc[k][1] = fmaf(gk[k], q1, acc[k][1]);
                acc[k][2] = fmaf(gk[k], q2, acc[k][2]);
            }
        }

        float cc0 = cs[tj*3+0], cc1 = cs[tj*3+1], cc2 = cs[tj*3+2];
#pragma unroll
        for (int k = 0; k < 8; k++) {
            int j = ti*8 + k;
            size_t ob = gb + (size_t)j*SS + tj*3;
            outd[ob+0] = (acc[k][0] - m2*cc0) * inv;
            outd[ob+1] = (acc[k][1] - m2*cc1) * inv;
            outd[ob+2] = (acc[k][2] - m2*cc2) * inv;
        }
    }
}

// ---------------- launch ----------------------------------------------------
extern "C" void kernel_launch(void* const* d_in, const int* in_sizes, int n_in,
                              void* d_out, int out_size) {
    const float* x  = (const float*)d_in[0];
    const float* g  = (const float*)d_in[1];
    const float* W1 = (const float*)d_in[2];
    const float* b1 = (const float*)d_in[3];
    const float* W2 = (const float*)d_in[4];
    const float* b2 = (const float*)d_in[5];

    float* out  = (float*)d_out;
    float* outp = out;
    float* outd = out + (size_t)TOTAL;

    cudaFuncSetAttribute(k_chanmix, cudaFuncAttributeMaxDynamicSharedMemorySize, CM_SMEM);
    cudaFuncSetAttribute(k_stats_d, cudaFuncAttributeMaxDynamicSharedMemorySize, SD_SMEM);
    cudaFuncSetAttribute(k_d,       cudaFuncAttributeMaxDynamicSharedMemorySize, KD_SMEM);

    { dim3 gg(GSS/128, BB); k_chanmix<<<gg, 128, CM_SMEM>>>(g, W2, b2, 1, GSS); }
    { dim3 gx(SS/128,  BB); k_chanmix<<<gx, 128, CM_SMEM>>>(x, W1, b1, 0, SS); }
    { dim3 gu(HH, BB*CC);   k_upsample<<<gu, dim3(24, 16)>>>(); }

    k_stats_d<<<NSITES/2, 128, SD_SMEM>>>();
    k_reduce_all<<<130, 256>>>();

    k_d<<<NSITES, 128, KD_SMEM>>>(x, outp, outd);
}

// round 11
// speedup vs baseline: 1.4617x; 1.4617x over previous
#include <cuda_runtime.h>

#define BB 2
#define CC 64
#define HH 48
#define WWn 48
#define LL 48
#define HWn (HH*WWn)            // 2304
#define SS (HH*WWn*LL)          // 110592
#define GHn 24
#define GSS (GHn*GHn*GHn)       // 13824
#define NSITES (BB*HWn)         // 4608
#define TOTAL (BB*CC*SS)        // 14155776

// ---------------- scratch ----------------
__device__ float g_tx[TOTAL];
__device__ float g_tg[TOTAL];
__device__ float g_tgl[BB*CC*GSS];
__device__ unsigned g_min_p_key;
__device__ unsigned g_min_d_key;
__device__ float g_sitechan[NSITES*CC];
__device__ float g_sitesum[NSITES];
__device__ float g_inv1[BB*CC];
__device__ float g_inv2[BB];

__device__ __forceinline__ unsigned fkey(float f) {
    unsigned u = __float_as_uint(f);
    return (u & 0x80000000u) ? ~u : (u | 0x80000000u);
}
__device__ __forceinline__ float funkey(unsigned k) {
    unsigned u = (k & 0x80000000u) ? (k ^ 0x80000000u) : ~k;
    return __uint_as_float(u);
}

// ---------------- channel-mix GEMM: 128 sites x 64 outs per block ----------
#define CM_SMEM ((64*68 + 64 + 64*132)*4)
__global__ __launch_bounds__(128, 4) void k_chanmix(
        const float* __restrict__ in, const float* __restrict__ Wm,
        const float* __restrict__ bias, int which, int Ssz) {
    extern __shared__ float dyn[];
    float* Wt  = dyn;             // 64*68
    float* bsm = Wt + 64*68;      // 64
    float* Xs  = bsm + 64;        // 64*132
    int tid = threadIdx.x;

    // fold the min-key init into the first kernel (g-side, block (0,0))
    if (which && blockIdx.x == 0 && blockIdx.y == 0 && tid == 0) {
        g_min_p_key = 0xFFFFFFFFu;
        g_min_d_key = 0xFFFFFFFFu;
    }

    for (int i = tid; i < 4096; i += 128) {
        int o = i >> 6, c = i & 63;
        Wt[c*68 + o] = Wm[i];
    }
    if (tid < 64) bsm[tid] = bias[tid];

    int b = blockIdx.y;
    size_t sbase = (size_t)b * CC * Ssz + (size_t)blockIdx.x * 128;
    const float* src = in + sbase;
    for (int i = tid; i < 64*32; i += 128) {
        int c = i >> 5, sv = i & 31;
        float4 v = *(const float4*)(src + (size_t)c*Ssz + sv*4);
        *(float4*)&Xs[c*132 + sv*4] = v;
    }
    __syncthreads();

    int og = tid & 3;
    int sg = tid >> 2;
    float acc[16][4];
#pragma unroll
    for (int j = 0; j < 16; j++) {
        float bv = bsm[og*16 + j];
        acc[j][0]=bv; acc[j][1]=bv; acc[j][2]=bv; acc[j][3]=bv;
    }

#pragma unroll 4
    for (int c = 0; c < 64; c++) {
        float4 xv = *(const float4*)&Xs[c*132 + sg*4];
        float xk[4] = {xv.x, xv.y, xv.z, xv.w};
#pragma unroll
        for (int q = 0; q < 4; q++) {
            float4 wv = *(const float4*)&Wt[c*68 + og*16 + q*4];
            float wk[4] = {wv.x, wv.y, wv.z, wv.w};
#pragma unroll
            for (int jj = 0; jj < 4; jj++)
#pragma unroll
                for (int kk = 0; kk < 4; kk++)
                    acc[q*4+jj][kk] = fmaf(wk[jj], xk[kk], acc[q*4+jj][kk]);
        }
    }

    float* outp = (which ? (float*)g_tgl : (float*)g_tx) + sbase;
#pragma unroll
    for (int j = 0; j < 16; j++) {
        int o = og*16 + j;
        float4 v = make_float4(acc[j][0], acc[j][1], acc[j][2], acc[j][3]);
        *(float4*)(outp + (size_t)o*Ssz + sg*4) = v;
    }
}

// ---------------- trilinear x2 upsample -------------------------------------
__global__ void k_upsample() {
    __shared__ float ph[24*25];
    int h  = blockIdx.x;
    int bc = blockIdx.y;

    int kh = h >> 1;
    int hf = (h & 1) ? (kh+1 > 23 ? 23 : kh+1) : (kh-1 < 0 ? 0 : kh-1);

    const float* bnear = g_tgl + (size_t)bc * GSS + kh*576;
    const float* bfar  = g_tgl + (size_t)bc * GSS + hf*576;
    int tid = threadIdx.y * 24 + threadIdx.x;
    for (int i = tid; i < 576; i += 384) {
        int wi = i / 24, li = i - wi*24;
        ph[wi*25 + li] = 0.75f*bnear[i] + 0.25f*bfar[i];
    }
    __syncthreads();

    int kl = threadIdx.x;
    int lm = kl-1 < 0 ? 0 : kl-1;
    int lp = kl+1 > 23 ? 23 : kl+1;

    float* orow = g_tg + (size_t)bc * SS + (size_t)h * HWn;
    for (int w = threadIdx.y; w < 48; w += 16) {
        int kw = w >> 1;
        int wf = (w & 1) ? (kw+1 > 23 ? 23 : kw+1) : (kw-1 < 0 ? 0 : kw-1);
        const float* rn = &ph[kw*25];
        const float* rf = &ph[wf*25];
        float um = 0.75f*rn[lm] + 0.25f*rf[lm];
        float uc = 0.75f*rn[kl] + 0.25f*rf[kl];
        float up = 0.75f*rn[lp] + 0.25f*rf[lp];
        float2 o;
        o.x = 0.25f*um + 0.75f*uc;
        o.y = 0.75f*uc + 0.25f*up;
        *(float2*)(orow + w*48 + 2*kl) = o;
    }
}

// ---- stats: raw = A*G^T per site (min+sum) AND elementwise tx*tg stats -----
// 256 threads, 2 sites per block; 128 threads per site, 4x8 tile per thread.
// Interleaved mapping (conflict-free, R9-verified): rows i = ti+16k, cols
// j = tj+8jj, row stride 52 floats -> bank stride 20, all 32 banks covered.
#define SD_SMEM (2*2*3328*4)
__global__ __launch_bounds__(256, 3) void k_stats_d() {
    extern __shared__ float dyn[];
    float* Ab = dyn;            // [2][3328]
    float* Gb = dyn + 2*3328;
    __shared__ float pp[256];
    __shared__ float rmin[8], rsum[8], pminw[8];
    int tid = threadIdx.x;

    for (int sj = 0; sj < 2; sj++) {
        int st = blockIdx.x*2 + sj;
        int b = st / HWn, hw = st - b*HWn;
        size_t gb = (size_t)b*CC*SS + (size_t)hw*LL;
        float* As = Ab + sj*3328;
        float* Gs = Gb + sj*3328;
        for (int i = tid; i < 768; i += 256) {
            int c = i / 12, lv = i - c*12;
            size_t off = gb + (size_t)c*SS + lv*4;
            *(float4*)&As[c*52 + lv*4] = *(const float4*)(g_tx + off);
            *(float4*)&Gs[c*52 + lv*4] = *(const float4*)(g_tg + off);
        }
    }
    __syncthreads();

    int sl = tid >> 7;          // site within block
    int s  = tid & 127;         // lane within site group
    const float* As = Ab + sl*3328;
    const float* Gs = Gb + sl*3328;

    // ---- p stats: 2 threads per channel-row, 24 elems each ----
    float pm = 3.402823466e38f;
    {
        int c = s >> 1, hf = s & 1;
        const float* Ar = &As[c*52 + hf*24];
        const float* Gr = &Gs[c*52 + hf*24];
        float ps = 0.f;
#pragma unroll
        for (int q = 0; q < 6; q++) {
            float4 a = *(const float4*)&Ar[q*4];
            float4 g = *(const float4*)&Gr[q*4];
            float t0 = a.x*g.x, t1 = a.y*g.y, t2 = a.z*g.z, t3 = a.w*g.w;
            ps += (t0+t1) + (t2+t3);
            pm = fminf(pm, fminf(fminf(t0,t1), fminf(t2,t3)));
        }
        pp[tid] = ps;
    }
#pragma unroll
    for (int off = 16; off; off >>= 1)
        pm = fminf(pm, __shfl_xor_sync(0xffffffffu, pm, off));
    if ((tid & 31) == 0) pminw[tid >> 5] = pm;

    // ---- raw = A*G^T : 4x8 tile per thread, interleaved mapping ----
    int ti = s >> 3;   // rows i = ti + 16*k, k=0..3
    int tj = s & 7;    // cols j = tj + 8*jj, jj=0..7

    float acc[4][8];
#pragma unroll
    for (int ii = 0; ii < 4; ii++)
#pragma unroll
        for (int jj = 0; jj < 8; jj++) acc[ii][jj] = 0.f;

    for (int l4 = 0; l4 < 12; l4++) {
        float4 av[4];
#pragma unroll
        for (int k = 0; k < 4; k++)
            av[k] = *(const float4*)&As[(ti + 16*k)*52 + l4*4];
#pragma unroll
        for (int jj = 0; jj < 8; jj++) {
            float4 gv = *(const float4*)&Gs[(tj + 8*jj)*52 + l4*4];
#pragma unroll
            for (int k = 0; k < 4; k++) {
                acc[k][jj] = fmaf(av[k].x, gv.x, acc[k][jj]);
                acc[k][jj] = fmaf(av[k].y, gv.y, acc[k][jj]);
                acc[k][jj] = fmaf(av[k].z, gv.z, acc[k][jj]);
                acc[k][jj] = fmaf(av[k].w, gv.w, acc[k][jj]);
            }
        }
    }

    float lmin = acc[0][0], lsum = 0.f;
#pragma unroll
    for (int ii = 0; ii < 4; ii++)
#pragma unroll
        for (int jj = 0; jj < 8; jj++) {
            lmin = fminf(lmin, acc[ii][jj]);
            lsum += acc[ii][jj];
        }
#pragma unroll
    for (int off = 16; off; off >>= 1) {
        lmin = fminf(lmin, __shfl_xor_sync(0xffffffffu, lmin, off));
        lsum += __shfl_xor_sync(0xffffffffu, lsum, off);
    }
    int wid = tid >> 5, lane = tid & 31;
    if (!lane) { rmin[wid] = lmin; rsum[wid] = lsum; }
    __syncthreads();

    // per-(site,channel) p sums: deterministic pairwise combine
    if (s < 64)
        g_sitechan[(size_t)(blockIdx.x*2 + sl)*64 + s] =
            pp[sl*128 + 2*s] + pp[sl*128 + 2*s + 1];

    if (s == 0)   // tid 0 (site 0) and tid 128 (site 1)
        g_sitesum[blockIdx.x*2 + sl] =
            (rsum[sl*4+0] + rsum[sl*4+1]) + (rsum[sl*4+2] + rsum[sl*4+3]);

    if (tid == 0) {
        float m = fminf(fminf(fminf(rmin[0], rmin[1]), fminf(rmin[2], rmin[3])),
                        fminf(fminf(rmin[4], rmin[5]), fminf(rmin[6], rmin[7])));
        atomicMin(&g_min_d_key, fkey(m));
        float pmn = fminf(fminf(fminf(pminw[0], pminw[1]), fminf(pminw[2], pminw[3])),
                          fminf(fminf(pminw[4], pminw[5]), fminf(pminw[6], pminw[7])));
        atomicMin(&g_min_p_key, fkey(pmn));
    }
}

// ------- merged reductions: blocks 0..127 = per-(b,c) p; 128..129 = d -------
__global__ void k_reduce_all() {
    __shared__ float sh[256];
    int tid = threadIdx.x;
    if (blockIdx.x < 128) {
        int bc = blockIdx.x;
        int b = bc >> 6, c = bc & 63;
        float s = 0.f;
        for (int i = tid; i < HWn; i += 256)
            s += g_sitechan[(size_t)(b*HWn + i)*64 + c];
        sh[tid] = s;
        __syncthreads();
        for (int st = 128; st > 0; st >>= 1) {
            if (tid < st) sh[tid] += sh[tid + st];
            __syncthreads();
        }
        if (tid == 0) {
            float m1 = funkey(g_min_p_key);
            g_inv1[bc] = 1.0f / (sh[0] - m1 * (float)SS);
        }
    } else {
        int b = blockIdx.x - 128;
        float s = 0.f;
        for (int i = tid; i < HWn; i += 256) s += g_sitesum[b * HWn + i];
        sh[tid] = s;
        __syncthreads();
        for (int st = 128; st > 0; st >>= 1) {
            if (tid < st) sh[tid] += sh[tid + st];
            __syncthreads();
        }
        if (tid == 0) {
            float m2 = funkey(g_min_d_key);
            g_inv2[b] = 1.0f / (sh[0] - m2 * 9437184.0f);
        }
    }
}

// -------- d (+ fused p): D = (G*(A^T X) - m2*colsum(X))*inv2 ----------------
// R7-exact proven configuration.
#define KD_SMEM ((3328 + 3328 + 3264 + 48)*4)
__global__ __launch_bounds__(128, 5) void k_d(const float* __restrict__ x,
                                              float* __restrict__ outp,
                                              float* __restrict__ outd) {
    extern __shared__ float dyn[];
    float* As = dyn;            // 64*52   (phase1 input; becomes Ms)
    float* Ms = dyn;            // 48*52   overlay
    float* Xs = As + 3328;      // 64*52
    float* Gt = Xs + 3328;      // 48*68 (transposed, swizzled)
    float* cs = Gt + 3264;      // 48
    int tid = threadIdx.x;
    int site = blockIdx.x;
    int b = site / HWn, hw = site - b*HWn;
    size_t gb = (size_t)b*CC*SS + (size_t)hw*LL;

    float m1 = funkey(g_min_p_key);
    for (int i = tid; i < 64*12; i += 128) {
        int c = i / 12, lv = i - c*12;
        size_t off = gb + (size_t)c*SS + lv*4;
        float4 a  = *(const float4*)(g_tx + off);
        float4 xv = *(const float4*)(x + off);
        float4 gg = *(const float4*)(g_tg + off);
        *(float4*)&As[c*52 + lv*4] = a;
        *(float4*)&Xs[c*52 + lv*4] = xv;
        {
            float gv[4] = {gg.x, gg.y, gg.z, gg.w};
#pragma unroll
            for (int q = 0; q < 4; q++) {
                int row = lv*4 + q;
                int colp = c ^ (8 * ((row >> 3) & 3));
                Gt[row*68 + colp] = gv[q];
            }
        }
        float inv1 = g_inv1[b*64 + c];
        float4 o;
        o.x = (a.x*gg.x - m1) * xv.x * inv1;
        o.y = (a.y*gg.y - m1) * xv.y * inv1;
        o.z = (a.z*gg.z - m1) * xv.z * inv1;
        o.w = (a.w*gg.w - m1) * xv.w * inv1;
        *(float4*)(outp + off) = o;
    }
    __syncthreads();

    if (tid < 48) {
        float s = 0.f;
#pragma unroll 8
        for (int c = 0; c < 64; c++) s += Xs[c*52 + tid];
        cs[tid] = s;
    }

    // phase 1: M[lp][l] = sum_c A[c][lp] * X[c][l] (accumulate in registers)
    float p1acc[3][6];
    int p1ti = tid >> 3;
    int p1tj = tid & 7;
    {
#pragma unroll
        for (int ii = 0; ii < 3; ii++)
#pragma unroll
            for (int jj = 0; jj < 6; jj++) p1acc[ii][jj] = 0.f;

#pragma unroll 4
        for (int c = 0; c < 64; c++) {
            float a0 = As[c*52 + p1ti*3 + 0];
            float a1 = As[c*52 + p1ti*3 + 1];
            float a2 = As[c*52 + p1ti*3 + 2];
            float xv[6];
#pragma unroll
            for (int jj = 0; jj < 6; jj++) xv[jj] = Xs[c*52 + p1tj*6 + jj];
#pragma unroll
            for (int jj = 0; jj < 6; jj++) {
                p1acc[0][jj] = fmaf(a0, xv[jj], p1acc[0][jj]);
                p1acc[1][jj] = fmaf(a1, xv[jj], p1acc[1][jj]);
                p1acc[2][jj] = fmaf(a2, xv[jj], p1acc[2][jj]);
            }
        }
    }
    __syncthreads();

#pragma unroll
    for (int ii = 0; ii < 3; ii++)
#pragma unroll
        for (int jj = 0; jj < 6; jj++)
            Ms[(p1ti*3+ii)*52 + p1tj*6 + jj] = p1acc[ii][jj];
    __syncthreads();

    // phase 2: D[j][l] = sum_lp Gt[lp][j] * M[lp][l]
    float m2  = funkey(g_min_d_key);
    float inv = g_inv2[b];
    {
        int ti = tid >> 4;
        int tj = tid & 15;
        float acc[8][3];
#pragma unroll
        for (int k = 0; k < 8; k++)
#pragma unroll
            for (int m = 0; m < 3; m++) acc[k][m] = 0.f;

#pragma unroll 4
        for (int lp = 0; lp < 48; lp++) {
            int jbase = (ti*8) ^ (8 * ((lp >> 3) & 3));
            float4 gA = *(const float4*)&Gt[lp*68 + jbase];
            float4 gB = *(const float4*)&Gt[lp*68 + jbase + 4];
            float gk[8] = {gA.x,gA.y,gA.z,gA.w,gB.x,gB.y,gB.z,gB.w};
            float q0 = Ms[lp*52 + tj*3 + 0];
            float q1 = Ms[lp*52 + tj*3 + 1];
            float q2 = Ms[lp*52 + tj*3 + 2];
#pragma unroll
            for (int k = 0; k < 8; k++) {
                acc[k][0] = fmaf(gk[k], q0, acc[k][0]);
                acc[k][1] = fmaf(gk[k], q1, acc[k][1]);
                acc[k][2] = fmaf(gk[k], q2, acc[k][2]);
            }
        }

        float cc0 = cs[tj*3+0], cc1 = cs[tj*3+1], cc2 = cs[tj*3+2];
#pragma unroll
        for (int k = 0; k < 8; k++) {
            int j = ti*8 + k;
            size_t ob = gb + (size_t)j*SS + tj*3;
            outd[ob+0] = (acc[k][0] - m2*cc0) * inv;
            outd[ob+1] = (acc[k][1] - m2*cc1) * inv;
            outd[ob+2] = (acc[k][2] - m2*cc2) * inv;
        }
    }
}

// ---------------- launch ----------------------------------------------------
extern "C" void kernel_launch(void* const* d_in, const int* in_sizes, int n_in,
                              void* d_out, int out_size) {
    const float* x  = (const float*)d_in[0];
    const float* g  = (const float*)d_in[1];
    const float* W1 = (const float*)d_in[2];
    const float* b1 = (const float*)d_in[3];
    const float* W2 = (const float*)d_in[4];
    const float* b2 = (const float*)d_in[5];

    float* out  = (float*)d_out;
    float* outp = out;
    float* outd = out + (size_t)TOTAL;

    cudaFuncSetAttribute(k_chanmix, cudaFuncAttributeMaxDynamicSharedMemorySize, CM_SMEM);
    cudaFuncSetAttribute(k_stats_d, cudaFuncAttributeMaxDynamicSharedMemorySize, SD_SMEM);
    cudaFuncSetAttribute(k_d,       cudaFuncAttributeMaxDynamicSharedMemorySize, KD_SMEM);

    { dim3 gg(GSS/128, BB); k_chanmix<<<gg, 128, CM_SMEM>>>(g, W2, b2, 1, GSS); }
    { dim3 gx(SS/128,  BB); k_chanmix<<<gx, 128, CM_SMEM>>>(x, W1, b1, 0, SS); }
    { dim3 gu(HH, BB*CC);   k_upsample<<<gu, dim3(24, 16)>>>(); }

    k_stats_d<<<NSITES/2, 256, SD_SMEM>>>();
    k_reduce_all<<<130, 256>>>();

    k_d<<<NSITES, 128, KD_SMEM>>>(x, outp, outd);
}